// round 5
// baseline (speedup 1.0000x reference)
#include <cuda_runtime.h>

// ---------------------------------------------------------------------------
// FCOS loss, 5 FPN levels, B=16, C=80 — single fused kernel.
// Level shapes: (100,128),(50,64),(25,32),(13,16),(7,8) -> HW: 12800,3200,800,208,56
//
// Input order detected at runtime from in_sizes (per-level vs type-grouped).
// Output: single f32 scalar.
//
// Structure: one grid. Blocks [0, FBLK) stream conf and sum the focal negative
// term; blocks [FBLK, TOTAL) handle per-pixel positive work. All accumulate
// into __device__ globals; the last block to arrive computes the final scalar
// and resets the globals to zero (so every graph replay starts identically).
// ---------------------------------------------------------------------------

#define NB 16          // batch
#define NC 80          // classes

// per-level HW
#define HW0 12800
#define HW1 3200
#define HW2 800
#define HW3 208
#define HW4 56

// per-level C*H*W in float4 units (C*HW/4)
#define CHWV0 256000
#define CHWV1 64000
#define CHWV2 16000
#define CHWV3 4160
#define CHWV4 1120

// focal tiling: 256 threads x 8 float4 per thread = 2048 vec4 per block
#define BVEC 2048
#define BLK0 125   // ceil(256000/2048)
#define BLK1 32    // ceil(64000/2048)
#define BLK2 8     // ceil(16000/2048)
#define BLK3 3     // ceil(4160/2048)
#define BLK4 1     // ceil(1120/2048)
#define CB1 (BLK0)
#define CB2 (CB1+BLK1)
#define CB3 (CB2+BLK2)
#define CB4 (CB3+BLK3)
#define NBLKX (CB4+BLK4)           // 169 per image
#define FBLK (NBLKX*NB)            // 2704 focal blocks

// pixel work: pixels per level across batch (B*HW), cumulative
#define P0 (NB*HW0)                // 204800
#define P1 (P0 + NB*HW1)           // 256000
#define P2 (P1 + NB*HW2)           // 268800
#define P3 (P2 + NB*HW3)           // 272128
#define P4 (P3 + NB*HW4)           // 273024
#define PIXBLK ((P4 + 255) / 256)  // 1067
#define TOTALBLK (FBLK + PIXBLK)   // 3771

// accumulators (device globals: zero at load, reset to zero by last block)
__device__ float    g_conf[NB];
__device__ float    g_loc[NB];
__device__ float    g_ctr[NB];
__device__ int      g_npos[NB];
__device__ unsigned g_count;

__device__ __forceinline__ float neg_focal(float p) {   // p^2 * log(1-p) (negative)
    float q = 1.0f - p;
    return p * p * __logf(q);
}
__device__ __forceinline__ float clipp(float p) {
    return fminf(fmaxf(p, 1e-8f), 0.99999999f);
}

// ---------------------------------------------------------------------------
__global__ __launch_bounds__(256) void fcos_fused_kernel(
    const float* __restrict__ c0, const float* __restrict__ c1,
    const float* __restrict__ c2, const float* __restrict__ c3,
    const float* __restrict__ c4,
    const float* __restrict__ l0, const float* __restrict__ l1,
    const float* __restrict__ l2, const float* __restrict__ l3,
    const float* __restrict__ l4,
    const float* __restrict__ ce0, const float* __restrict__ ce1,
    const float* __restrict__ ce2, const float* __restrict__ ce3,
    const float* __restrict__ ce4,
    const float* __restrict__ t0, const float* __restrict__ t1,
    const float* __restrict__ t2, const float* __restrict__ t3,
    const float* __restrict__ t4,
    const int* __restrict__ k0, const int* __restrict__ k1,
    const int* __restrict__ k2, const int* __restrict__ k3,
    const int* __restrict__ k4,
    const int* __restrict__ m0, const int* __restrict__ m1,
    const int* __restrict__ m2, const int* __restrict__ m3,
    const int* __restrict__ m4,
    float* __restrict__ out)
{
    __shared__ float s_conf[NB], s_loc[NB], s_ctr[NB];
    __shared__ int   s_np[NB];
    __shared__ float sred[8];
    __shared__ int   s_last;

    const int bid = blockIdx.x;
    const int tid = threadIdx.x;

    if (bid < FBLK) {
        // ================= focal negative-term streaming =================
        const int b  = bid / NBLKX;
        const int bx = bid - b * NBLKX;

        const float4* __restrict__ cp;
        int chwv, inner;
        if (bx < CB1)      { cp = (const float4*)c0; chwv = CHWV0; inner = bx;       }
        else if (bx < CB2) { cp = (const float4*)c1; chwv = CHWV1; inner = bx - CB1; }
        else if (bx < CB3) { cp = (const float4*)c2; chwv = CHWV2; inner = bx - CB2; }
        else if (bx < CB4) { cp = (const float4*)c3; chwv = CHWV3; inner = bx - CB3; }
        else               { cp = (const float4*)c4; chwv = CHWV4; inner = bx - CB4; }

        cp += (long)b * chwv;
        const int base = inner * BVEC + tid;

        float acc = 0.0f;
        #pragma unroll
        for (int k = 0; k < 8; k++) {
            int v = base + k * 256;
            if (v < chwv) {
                float4 p = cp[v];
                acc += neg_focal(clipp(p.x)) + neg_focal(clipp(p.y))
                     + neg_focal(clipp(p.z)) + neg_focal(clipp(p.w));
            }
        }
        acc *= -0.75f;   // -(1-ALPHA), sign flip -> positive loss

        #pragma unroll
        for (int o = 16; o > 0; o >>= 1)
            acc += __shfl_down_sync(0xffffffffu, acc, o);
        const int lane = tid & 31, wid = tid >> 5;
        if (lane == 0) sred[wid] = acc;
        __syncthreads();
        if (tid < 8) {
            float v = sred[tid];
            #pragma unroll
            for (int o = 4; o > 0; o >>= 1)
                v += __shfl_down_sync(0xffu, v, o);
            if (tid == 0) atomicAdd(&g_conf[b], v);
        }
    } else {
        // ================= sparse positive-pixel work =================
        if (tid < NB) {
            s_conf[tid] = 0.0f; s_loc[tid] = 0.0f; s_ctr[tid] = 0.0f; s_np[tid] = 0;
        }
        __syncthreads();

        const int id = (bid - FBLK) * 256 + tid;
        if (id < P4) {
            const float *conf, *loc, *ctr, *ltrb;
            const int *cls, *pos;
            int HW, i;
            if (id < P0)      { conf=c0; loc=l0; ctr=ce0; ltrb=t0; cls=k0; pos=m0; HW=HW0; i=id;    }
            else if (id < P1) { conf=c1; loc=l1; ctr=ce1; ltrb=t1; cls=k1; pos=m1; HW=HW1; i=id-P0; }
            else if (id < P2) { conf=c2; loc=l2; ctr=ce2; ltrb=t2; cls=k2; pos=m2; HW=HW2; i=id-P1; }
            else if (id < P3) { conf=c3; loc=l3; ctr=ce3; ltrb=t3; cls=k3; pos=m3; HW=HW3; i=id-P2; }
            else              { conf=c4; loc=l4; ctr=ce4; ltrb=t4; cls=k4; pos=m4; HW=HW4; i=id-P3; }

            const int b   = i / HW;
            const int pix = i - b * HW;
            const long pbase = (long)b * HW + pix;

            if (pos[pbase] == 0) {
                // focal correction at (b, cls, pix): pos - neg
                const int c = cls[pbase];
                float p = clipp(conf[((long)b * NC + c) * HW + pix]);
                float q = 1.0f - p;
                float corr = -0.25f * q * q * __logf(p) + 0.75f * p * p * __logf(q);

                // IoU loss
                const long o = (long)b * 4 * HW + pix;
                float lp = loc[o]           * 32.0f;
                float tp = loc[o + HW]      * 32.0f;
                float rp = loc[o + 2 * HW]  * 32.0f;
                float bp = loc[o + 3 * HW]  * 32.0f;
                float lt = ltrb[o]          * 32.0f;
                float tt = ltrb[o + HW]     * 32.0f;
                float rt = ltrb[o + 2 * HW] * 32.0f;
                float bt = ltrb[o + 3 * HW] * 32.0f;

                float iw = fmaxf(fminf(lp, lt) + fminf(rp, rt), 0.0f);
                float ih = fmaxf(fminf(tp, tt) + fminf(bp, bt), 0.0f);
                float inter  = iw * ih;
                float area_p = fmaxf(lp + rp, 0.0f) * fmaxf(tp + bp, 0.0f);
                float area_t = (lt + rt) * (tt + bt);
                float iou = inter / (area_p + area_t - inter + 1e-6f);
                float loss_l = -__logf(iou + 1e-6f);

                // centerness BCE
                float ctr_t = sqrtf((fminf(lt, rt) / (fmaxf(lt, rt) + 1e-6f)) *
                                    (fminf(tt, bt) / (fmaxf(tt, bt) + 1e-6f)));
                float cp = ctr[pbase];
                cp = fminf(fmaxf(cp, 1e-8f), 1.0f - 1e-8f);
                float bce = -(ctr_t * __logf(cp) + (1.0f - ctr_t) * __logf(1.0f - cp));

                atomicAdd(&s_conf[b], corr);
                atomicAdd(&s_loc[b],  loss_l);
                atomicAdd(&s_ctr[b],  bce);
                atomicAdd(&s_np[b],   1);
            }
        }
        __syncthreads();

        if (tid < NB) {
            if (s_conf[tid] != 0.0f) atomicAdd(&g_conf[tid], s_conf[tid]);
            if (s_loc[tid]  != 0.0f) atomicAdd(&g_loc[tid],  s_loc[tid]);
            if (s_ctr[tid]  != 0.0f) atomicAdd(&g_ctr[tid],  s_ctr[tid]);
            if (s_np[tid])           atomicAdd(&g_npos[tid], s_np[tid]);
        }
    }

    // ================= completion: last block finalizes =================
    __threadfence();
    __syncthreads();
    if (tid == 0)
        s_last = (atomicAdd(&g_count, 1u) == (unsigned)(TOTALBLK - 1));
    __syncthreads();

    if (s_last && tid < 32) {
        __threadfence();   // acquire: see all other blocks' atomics
        volatile float* vconf = g_conf;
        volatile float* vloc  = g_loc;
        volatile float* vctr  = g_ctr;
        volatile int*   vnp   = g_npos;

        float v = 0.0f;
        if (tid < NB) {
            float lc = vconf[tid], ll = vloc[tid], lctr = vctr[tid];
            int   np = vnp[tid];
            float pf = (float)np;
            v = (np > 0) ? (lctr + (lc + ll) / fmaxf(pf, 1.0f))
                         : (lctr + lc + ll);
        }
        #pragma unroll
        for (int o = 16; o > 0; o >>= 1)
            v += __shfl_down_sync(0xffffffffu, v, o);
        if (tid == 0) out[0] = v * (1.0f / (float)NB);

        // reset state for the next invocation / graph replay
        if (tid < NB) {
            vconf[tid] = 0.0f; vloc[tid] = 0.0f; vctr[tid] = 0.0f; vnp[tid] = 0;
        }
        __threadfence();
        if (tid == 0) g_count = 0u;
    }
}

// ---------------------------------------------------------------------------
extern "C" void kernel_launch(void* const* d_in, const int* in_sizes, int n_in,
                              void* d_out, int out_size)
{
    (void)n_in; (void)out_size;

    // Runtime input-order detection.
    // Per-level order:    in_sizes[1] = 16*4*12800 = 819200   (loc0)
    // Type-grouped order: in_sizes[1] = 16*80*3200 = 4096000  (conf1)
    int iconf[5], iloc[5], ictr[5], iltrb[5], icls[5], ipos[5];
    if (in_sizes[1] == 16 * 4 * 12800) {
        for (int l = 0; l < 5; l++) {
            iconf[l] = 6 * l + 0; iloc[l] = 6 * l + 1; ictr[l] = 6 * l + 2;
            iltrb[l] = 6 * l + 3; icls[l] = 6 * l + 4; ipos[l] = 6 * l + 5;
        }
    } else {
        for (int l = 0; l < 5; l++) {
            iconf[l] = l; iloc[l] = 5 + l; ictr[l] = 10 + l;
            iltrb[l] = 15 + l; icls[l] = 20 + l; ipos[l] = 25 + l;
        }
    }

    fcos_fused_kernel<<<TOTALBLK, 256>>>(
        (const float*)d_in[iconf[0]], (const float*)d_in[iconf[1]],
        (const float*)d_in[iconf[2]], (const float*)d_in[iconf[3]],
        (const float*)d_in[iconf[4]],
        (const float*)d_in[iloc[0]],  (const float*)d_in[iloc[1]],
        (const float*)d_in[iloc[2]],  (const float*)d_in[iloc[3]],
        (const float*)d_in[iloc[4]],
        (const float*)d_in[ictr[0]],  (const float*)d_in[ictr[1]],
        (const float*)d_in[ictr[2]],  (const float*)d_in[ictr[3]],
        (const float*)d_in[ictr[4]],
        (const float*)d_in[iltrb[0]], (const float*)d_in[iltrb[1]],
        (const float*)d_in[iltrb[2]], (const float*)d_in[iltrb[3]],
        (const float*)d_in[iltrb[4]],
        (const int*)d_in[icls[0]], (const int*)d_in[icls[1]],
        (const int*)d_in[icls[2]], (const int*)d_in[icls[3]],
        (const int*)d_in[icls[4]],
        (const int*)d_in[ipos[0]], (const int*)d_in[ipos[1]],
        (const int*)d_in[ipos[2]], (const int*)d_in[ipos[3]],
        (const int*)d_in[ipos[4]],
        (float*)d_out);
}

// round 6
// speedup vs baseline: 1.2476x; 1.2476x over previous
#include <cuda_runtime.h>

// ---------------------------------------------------------------------------
// FCOS loss, 5 FPN levels, B=16, C=80 — two launches.
// Kernel A: one grid; blocks [0,PIXBLK) do sparse positive-pixel work,
//           blocks [PIXBLK,TOTAL) stream conf for the focal negative term.
//           All accumulate into __device__ globals with atomics.
// Kernel B: 1 block; combines accumulators -> scalar, then resets them to 0
//           (so state is identical before every graph replay).
// ---------------------------------------------------------------------------

#define NB 16          // batch
#define NC 80          // classes

// per-level HW
#define HW0 12800
#define HW1 3200
#define HW2 800
#define HW3 208
#define HW4 56

// per-level C*H*W in float4 units (C*HW/4)
#define CHWV0 256000
#define CHWV1 64000
#define CHWV2 16000
#define CHWV3 4160
#define CHWV4 1120

// focal tiling: 256 threads x 8 float4 per thread = 2048 vec4 per block
#define BVEC 2048
#define BLK0 125   // ceil(256000/2048)
#define BLK1 32
#define BLK2 8
#define BLK3 3
#define BLK4 1
#define CB1 (BLK0)
#define CB2 (CB1+BLK1)
#define CB3 (CB2+BLK2)
#define CB4 (CB3+BLK3)
#define NBLKX (CB4+BLK4)           // 169 per image
#define FBLK (NBLKX*NB)            // 2704 focal blocks

// pixel work: pixels per level across batch (B*HW), cumulative
#define P0 (NB*HW0)                // 204800
#define P1 (P0 + NB*HW1)           // 256000
#define P2 (P1 + NB*HW2)           // 268800
#define P3 (P2 + NB*HW3)           // 272128
#define P4 (P3 + NB*HW4)           // 273024
#define PIXBLK ((P4 + 255) / 256)  // 1067
#define TOTALBLK (FBLK + PIXBLK)   // 3771

// 0.75 * ln(2): folds -(1-ALPHA) and the log2->ln conversion
#define NEG_SCALE (-0.519860385f)

// accumulators (device globals: zero at load, reset to zero by kernel B)
__device__ float g_conf[NB];
__device__ float g_loc[NB];
__device__ float g_ctr[NB];
__device__ int   g_npos[NB];

__device__ __forceinline__ float clipp(float p) {
    return fminf(fmaxf(p, 1e-8f), 0.99999999f);
}

// ---------------------------------------------------------------------------
__global__ __launch_bounds__(256) void fcos_work_kernel(
    const float* __restrict__ c0, const float* __restrict__ c1,
    const float* __restrict__ c2, const float* __restrict__ c3,
    const float* __restrict__ c4,
    const float* __restrict__ l0, const float* __restrict__ l1,
    const float* __restrict__ l2, const float* __restrict__ l3,
    const float* __restrict__ l4,
    const float* __restrict__ ce0, const float* __restrict__ ce1,
    const float* __restrict__ ce2, const float* __restrict__ ce3,
    const float* __restrict__ ce4,
    const float* __restrict__ t0, const float* __restrict__ t1,
    const float* __restrict__ t2, const float* __restrict__ t3,
    const float* __restrict__ t4,
    const int* __restrict__ k0, const int* __restrict__ k1,
    const int* __restrict__ k2, const int* __restrict__ k3,
    const int* __restrict__ k4,
    const int* __restrict__ m0, const int* __restrict__ m1,
    const int* __restrict__ m2, const int* __restrict__ m3,
    const int* __restrict__ m4)
{
    const int bid = blockIdx.x;
    const int tid = threadIdx.x;

    if (bid >= PIXBLK) {
        // ================= focal negative-term streaming =================
        const int fb = bid - PIXBLK;
        const int b  = fb / NBLKX;
        const int bx = fb - b * NBLKX;

        const float4* __restrict__ cp;
        int chwv, inner;
        if (bx < CB1)      { cp = (const float4*)c0; chwv = CHWV0; inner = bx;       }
        else if (bx < CB2) { cp = (const float4*)c1; chwv = CHWV1; inner = bx - CB1; }
        else if (bx < CB3) { cp = (const float4*)c2; chwv = CHWV2; inner = bx - CB2; }
        else if (bx < CB4) { cp = (const float4*)c3; chwv = CHWV3; inner = bx - CB3; }
        else               { cp = (const float4*)c4; chwv = CHWV4; inner = bx - CB4; }

        cp += (long)b * chwv;
        const int base = inner * BVEC + tid;

        // acc accumulates p^2 * log2(1-p); scale by 0.75*ln2 (negated) at the end.
        // No clipping needed in-stream: p ∈ [0,1) so 1-p > 0, and the reference's
        // clip bounds change the value by < 1e-16 per element.
        float acc = 0.0f;
        #pragma unroll
        for (int k = 0; k < 8; k++) {
            int v = base + k * 256;
            if (v < chwv) {
                float4 p = cp[v];
                acc += p.x * p.x * __log2f(1.0f - p.x)
                     + p.y * p.y * __log2f(1.0f - p.y)
                     + p.z * p.z * __log2f(1.0f - p.z)
                     + p.w * p.w * __log2f(1.0f - p.w);
            }
        }
        acc *= NEG_SCALE;   // -(1-ALPHA)*ln2 : positive loss contribution

        #pragma unroll
        for (int o = 16; o > 0; o >>= 1)
            acc += __shfl_down_sync(0xffffffffu, acc, o);
        __shared__ float sred[8];
        const int lane = tid & 31, wid = tid >> 5;
        if (lane == 0) sred[wid] = acc;
        __syncthreads();
        if (tid < 8) {
            float v = sred[tid];
            #pragma unroll
            for (int o = 4; o > 0; o >>= 1)
                v += __shfl_down_sync(0xffu, v, o);
            if (tid == 0) atomicAdd(&g_conf[b], v);
        }
    } else {
        // ================= sparse positive-pixel work =================
        __shared__ float s_conf[NB], s_loc[NB], s_ctr[NB];
        __shared__ int   s_np[NB];
        if (tid < NB) {
            s_conf[tid] = 0.0f; s_loc[tid] = 0.0f; s_ctr[tid] = 0.0f; s_np[tid] = 0;
        }
        __syncthreads();

        const int id = bid * 256 + tid;
        if (id < P4) {
            const float *conf, *loc, *ctr, *ltrb;
            const int *cls, *pos;
            int HW, i;
            if (id < P0)      { conf=c0; loc=l0; ctr=ce0; ltrb=t0; cls=k0; pos=m0; HW=HW0; i=id;    }
            else if (id < P1) { conf=c1; loc=l1; ctr=ce1; ltrb=t1; cls=k1; pos=m1; HW=HW1; i=id-P0; }
            else if (id < P2) { conf=c2; loc=l2; ctr=ce2; ltrb=t2; cls=k2; pos=m2; HW=HW2; i=id-P1; }
            else if (id < P3) { conf=c3; loc=l3; ctr=ce3; ltrb=t3; cls=k3; pos=m3; HW=HW3; i=id-P2; }
            else              { conf=c4; loc=l4; ctr=ce4; ltrb=t4; cls=k4; pos=m4; HW=HW4; i=id-P3; }

            const int b   = i / HW;
            const int pix = i - b * HW;
            const long pbase = (long)b * HW + pix;

            if (pos[pbase] == 0) {
                // focal correction at (b, cls, pix): pos - neg  (full clipped form)
                const int c = cls[pbase];
                float p = clipp(conf[((long)b * NC + c) * HW + pix]);
                float q = 1.0f - p;
                float corr = -0.25f * q * q * __logf(p) + 0.75f * p * p * __logf(q);

                // IoU loss
                const long o = (long)b * 4 * HW + pix;
                float lp = loc[o]           * 32.0f;
                float tp = loc[o + HW]      * 32.0f;
                float rp = loc[o + 2 * HW]  * 32.0f;
                float bp = loc[o + 3 * HW]  * 32.0f;
                float lt = ltrb[o]          * 32.0f;
                float tt = ltrb[o + HW]     * 32.0f;
                float rt = ltrb[o + 2 * HW] * 32.0f;
                float bt = ltrb[o + 3 * HW] * 32.0f;

                float iw = fmaxf(fminf(lp, lt) + fminf(rp, rt), 0.0f);
                float ih = fmaxf(fminf(tp, tt) + fminf(bp, bt), 0.0f);
                float inter  = iw * ih;
                float area_p = fmaxf(lp + rp, 0.0f) * fmaxf(tp + bp, 0.0f);
                float area_t = (lt + rt) * (tt + bt);
                float iou = inter / (area_p + area_t - inter + 1e-6f);
                float loss_l = -__logf(iou + 1e-6f);

                // centerness BCE
                float ctr_t = sqrtf((fminf(lt, rt) / (fmaxf(lt, rt) + 1e-6f)) *
                                    (fminf(tt, bt) / (fmaxf(tt, bt) + 1e-6f)));
                float cp = ctr[pbase];
                cp = fminf(fmaxf(cp, 1e-8f), 1.0f - 1e-8f);
                float bce = -(ctr_t * __logf(cp) + (1.0f - ctr_t) * __logf(1.0f - cp));

                atomicAdd(&s_conf[b], corr);
                atomicAdd(&s_loc[b],  loss_l);
                atomicAdd(&s_ctr[b],  bce);
                atomicAdd(&s_np[b],   1);
            }
        }
        __syncthreads();

        if (tid < NB) {
            if (s_conf[tid] != 0.0f) atomicAdd(&g_conf[tid], s_conf[tid]);
            if (s_loc[tid]  != 0.0f) atomicAdd(&g_loc[tid],  s_loc[tid]);
            if (s_ctr[tid]  != 0.0f) atomicAdd(&g_ctr[tid],  s_ctr[tid]);
            if (s_np[tid])           atomicAdd(&g_npos[tid], s_np[tid]);
        }
    }
}

// ---------------------------------------------------------------------------
// Kernel B: combine to the final scalar, then reset accumulators to zero so
// every invocation (graph replay) starts from identical state.
__global__ void fcos_final_kernel(float* __restrict__ out) {
    const int t = threadIdx.x;
    float v = 0.0f;
    if (t < NB) {
        float lc = g_conf[t], ll = g_loc[t], lctr = g_ctr[t];
        int   np = g_npos[t];
        float pf = (float)np;
        v = (np > 0) ? (lctr + (lc + ll) / fmaxf(pf, 1.0f))
                     : (lctr + lc + ll);
        g_conf[t] = 0.0f; g_loc[t] = 0.0f; g_ctr[t] = 0.0f; g_npos[t] = 0;
    }
    #pragma unroll
    for (int o = 16; o > 0; o >>= 1)
        v += __shfl_down_sync(0xffffffffu, v, o);
    if (t == 0) out[0] = v * (1.0f / (float)NB);
}

// ---------------------------------------------------------------------------
extern "C" void kernel_launch(void* const* d_in, const int* in_sizes, int n_in,
                              void* d_out, int out_size)
{
    (void)n_in; (void)out_size;

    // Runtime input-order detection.
    // Per-level order:    in_sizes[1] = 16*4*12800 = 819200   (loc0)
    // Type-grouped order: in_sizes[1] = 16*80*3200 = 4096000  (conf1)
    int iconf[5], iloc[5], ictr[5], iltrb[5], icls[5], ipos[5];
    if (in_sizes[1] == 16 * 4 * 12800) {
        for (int l = 0; l < 5; l++) {
            iconf[l] = 6 * l + 0; iloc[l] = 6 * l + 1; ictr[l] = 6 * l + 2;
            iltrb[l] = 6 * l + 3; icls[l] = 6 * l + 4; ipos[l] = 6 * l + 5;
        }
    } else {
        for (int l = 0; l < 5; l++) {
            iconf[l] = l; iloc[l] = 5 + l; ictr[l] = 10 + l;
            iltrb[l] = 15 + l; icls[l] = 20 + l; ipos[l] = 25 + l;
        }
    }

    fcos_work_kernel<<<TOTALBLK, 256>>>(
        (const float*)d_in[iconf[0]], (const float*)d_in[iconf[1]],
        (const float*)d_in[iconf[2]], (const float*)d_in[iconf[3]],
        (const float*)d_in[iconf[4]],
        (const float*)d_in[iloc[0]],  (const float*)d_in[iloc[1]],
        (const float*)d_in[iloc[2]],  (const float*)d_in[iloc[3]],
        (const float*)d_in[iloc[4]],
        (const float*)d_in[ictr[0]],  (const float*)d_in[ictr[1]],
        (const float*)d_in[ictr[2]],  (const float*)d_in[ictr[3]],
        (const float*)d_in[ictr[4]],
        (const float*)d_in[iltrb[0]], (const float*)d_in[iltrb[1]],
        (const float*)d_in[iltrb[2]], (const float*)d_in[iltrb[3]],
        (const float*)d_in[iltrb[4]],
        (const int*)d_in[icls[0]], (const int*)d_in[icls[1]],
        (const int*)d_in[icls[2]], (const int*)d_in[icls[3]],
        (const int*)d_in[icls[4]],
        (const int*)d_in[ipos[0]], (const int*)d_in[ipos[1]],
        (const int*)d_in[ipos[2]], (const int*)d_in[ipos[3]],
        (const int*)d_in[ipos[4]]);

    fcos_final_kernel<<<1, 32>>>((float*)d_out);
}

// round 7
// speedup vs baseline: 1.2597x; 1.0097x over previous
#include <cuda_runtime.h>

// ---------------------------------------------------------------------------
// FCOS loss, 5 FPN levels, B=16, C=80 — single kernel, cheap completion.
// Blocks [0,PIXBLK): sparse positive-pixel work.
// Blocks [PIXBLK,TOTAL): stream conf, sum focal negative term.
// All accumulate into __device__ globals via atomics. Only the atomic-issuing
// warp fences (1 MEMBAR/block, not per-thread). Last block to bump the arrival
// counter finalizes the scalar and resets all state to zero (so every graph
// replay starts from identical state).
// ---------------------------------------------------------------------------

#define NB 16          // batch
#define NC 80          // classes

// per-level HW
#define HW0 12800
#define HW1 3200
#define HW2 800
#define HW3 208
#define HW4 56

// per-level C*H*W in float4 units (C*HW/4)
#define CHWV0 256000
#define CHWV1 64000
#define CHWV2 16000
#define CHWV3 4160
#define CHWV4 1120

// focal tiling: 256 threads x 8 float4 per thread = 2048 vec4 per block
#define BVEC 2048
#define BLK0 125
#define BLK1 32
#define BLK2 8
#define BLK3 3
#define BLK4 1
#define CB1 (BLK0)
#define CB2 (CB1+BLK1)
#define CB3 (CB2+BLK2)
#define CB4 (CB3+BLK3)
#define NBLKX (CB4+BLK4)           // 169 per image
#define FBLK (NBLKX*NB)            // 2704 focal blocks

// pixel work: pixels per level across batch (B*HW), cumulative
#define P0 (NB*HW0)                // 204800
#define P1 (P0 + NB*HW1)           // 256000
#define P2 (P1 + NB*HW2)           // 268800
#define P3 (P2 + NB*HW3)           // 272128
#define P4 (P3 + NB*HW4)           // 273024
#define PIXBLK ((P4 + 255) / 256)  // 1067
#define TOTALBLK (FBLK + PIXBLK)   // 3771

// 0.75 * ln(2): folds -(1-ALPHA) and the log2->ln conversion
#define NEG_SCALE (-0.519860385f)

// accumulators (device globals: zero at load, reset to zero by last block)
__device__ float    g_conf[NB];
__device__ float    g_loc[NB];
__device__ float    g_ctr[NB];
__device__ int      g_npos[NB];
__device__ unsigned g_count;

__device__ __forceinline__ float clipp(float p) {
    return fminf(fmaxf(p, 1e-8f), 0.99999999f);
}

// ---------------------------------------------------------------------------
__global__ __launch_bounds__(256) void fcos_work_kernel(
    const float* __restrict__ c0, const float* __restrict__ c1,
    const float* __restrict__ c2, const float* __restrict__ c3,
    const float* __restrict__ c4,
    const float* __restrict__ l0, const float* __restrict__ l1,
    const float* __restrict__ l2, const float* __restrict__ l3,
    const float* __restrict__ l4,
    const float* __restrict__ ce0, const float* __restrict__ ce1,
    const float* __restrict__ ce2, const float* __restrict__ ce3,
    const float* __restrict__ ce4,
    const float* __restrict__ t0, const float* __restrict__ t1,
    const float* __restrict__ t2, const float* __restrict__ t3,
    const float* __restrict__ t4,
    const int* __restrict__ k0, const int* __restrict__ k1,
    const int* __restrict__ k2, const int* __restrict__ k3,
    const int* __restrict__ k4,
    const int* __restrict__ m0, const int* __restrict__ m1,
    const int* __restrict__ m2, const int* __restrict__ m3,
    const int* __restrict__ m4,
    float* __restrict__ out)
{
    __shared__ int s_last;
    const int bid = blockIdx.x;
    const int tid = threadIdx.x;

    if (bid >= PIXBLK) {
        // ================= focal negative-term streaming =================
        const int fb = bid - PIXBLK;
        const int b  = fb / NBLKX;
        const int bx = fb - b * NBLKX;

        const float4* __restrict__ cp;
        int chwv, inner;
        if (bx < CB1)      { cp = (const float4*)c0; chwv = CHWV0; inner = bx;       }
        else if (bx < CB2) { cp = (const float4*)c1; chwv = CHWV1; inner = bx - CB1; }
        else if (bx < CB3) { cp = (const float4*)c2; chwv = CHWV2; inner = bx - CB2; }
        else if (bx < CB4) { cp = (const float4*)c3; chwv = CHWV3; inner = bx - CB3; }
        else               { cp = (const float4*)c4; chwv = CHWV4; inner = bx - CB4; }

        cp += (long)b * chwv;
        const int base = inner * BVEC + tid;

        // acc accumulates p^2 * log2(1-p); scaled by -(0.75*ln2) at the end.
        // (No in-stream clipping: p in [0,1); effect of the clip is < 1e-16.)
        float acc = 0.0f;
        if (inner * BVEC + BVEC <= chwv) {
            // fast path: full tile — front-batch all 8 LDG.128 for max MLP
            float4 r[8];
            #pragma unroll
            for (int k = 0; k < 8; k++) r[k] = cp[base + k * 256];
            #pragma unroll
            for (int k = 0; k < 8; k++) {
                float4 p = r[k];
                acc += p.x * p.x * __log2f(1.0f - p.x)
                     + p.y * p.y * __log2f(1.0f - p.y)
                     + p.z * p.z * __log2f(1.0f - p.z)
                     + p.w * p.w * __log2f(1.0f - p.w);
            }
        } else {
            #pragma unroll
            for (int k = 0; k < 8; k++) {
                int v = base + k * 256;
                if (v < chwv) {
                    float4 p = cp[v];
                    acc += p.x * p.x * __log2f(1.0f - p.x)
                         + p.y * p.y * __log2f(1.0f - p.y)
                         + p.z * p.z * __log2f(1.0f - p.z)
                         + p.w * p.w * __log2f(1.0f - p.w);
                }
            }
        }
        acc *= NEG_SCALE;

        #pragma unroll
        for (int o = 16; o > 0; o >>= 1)
            acc += __shfl_down_sync(0xffffffffu, acc, o);
        __shared__ float sred[8];
        const int lane = tid & 31, wid = tid >> 5;
        if (lane == 0) sred[wid] = acc;
        __syncthreads();
        if (tid < 8) {
            float v = sred[tid];
            #pragma unroll
            for (int o = 4; o > 0; o >>= 1)
                v += __shfl_down_sync(0xffu, v, o);
            if (tid == 0) {
                atomicAdd(&g_conf[b], v);
                __threadfence();   // release my contribution (1 thread/block)
            }
        }
    } else {
        // ================= sparse positive-pixel work =================
        __shared__ float s_conf[NB], s_loc[NB], s_ctr[NB];
        __shared__ int   s_np[NB];
        if (tid < NB) {
            s_conf[tid] = 0.0f; s_loc[tid] = 0.0f; s_ctr[tid] = 0.0f; s_np[tid] = 0;
        }
        __syncthreads();

        const int id = bid * 256 + tid;
        if (id < P4) {
            const float *conf, *loc, *ctr, *ltrb;
            const int *cls, *pos;
            int HW, i;
            if (id < P0)      { conf=c0; loc=l0; ctr=ce0; ltrb=t0; cls=k0; pos=m0; HW=HW0; i=id;    }
            else if (id < P1) { conf=c1; loc=l1; ctr=ce1; ltrb=t1; cls=k1; pos=m1; HW=HW1; i=id-P0; }
            else if (id < P2) { conf=c2; loc=l2; ctr=ce2; ltrb=t2; cls=k2; pos=m2; HW=HW2; i=id-P1; }
            else if (id < P3) { conf=c3; loc=l3; ctr=ce3; ltrb=t3; cls=k3; pos=m3; HW=HW3; i=id-P2; }
            else              { conf=c4; loc=l4; ctr=ce4; ltrb=t4; cls=k4; pos=m4; HW=HW4; i=id-P3; }

            const int b   = i / HW;
            const int pix = i - b * HW;
            const long pbase = (long)b * HW + pix;

            if (pos[pbase] == 0) {
                // focal correction at (b, cls, pix): pos - neg (full clipped form)
                const int c = cls[pbase];
                float p = clipp(conf[((long)b * NC + c) * HW + pix]);
                float q = 1.0f - p;
                float corr = -0.25f * q * q * __logf(p) + 0.75f * p * p * __logf(q);

                // IoU loss
                const long o = (long)b * 4 * HW + pix;
                float lp = loc[o]           * 32.0f;
                float tp = loc[o + HW]      * 32.0f;
                float rp = loc[o + 2 * HW]  * 32.0f;
                float bp = loc[o + 3 * HW]  * 32.0f;
                float lt = ltrb[o]          * 32.0f;
                float tt = ltrb[o + HW]     * 32.0f;
                float rt = ltrb[o + 2 * HW] * 32.0f;
                float bt = ltrb[o + 3 * HW] * 32.0f;

                float iw = fmaxf(fminf(lp, lt) + fminf(rp, rt), 0.0f);
                float ih = fmaxf(fminf(tp, tt) + fminf(bp, bt), 0.0f);
                float inter  = iw * ih;
                float area_p = fmaxf(lp + rp, 0.0f) * fmaxf(tp + bp, 0.0f);
                float area_t = (lt + rt) * (tt + bt);
                float iou = inter / (area_p + area_t - inter + 1e-6f);
                float loss_l = -__logf(iou + 1e-6f);

                // centerness BCE
                float ctr_t = sqrtf((fminf(lt, rt) / (fmaxf(lt, rt) + 1e-6f)) *
                                    (fminf(tt, bt) / (fmaxf(tt, bt) + 1e-6f)));
                float cp = ctr[pbase];
                cp = fminf(fmaxf(cp, 1e-8f), 1.0f - 1e-8f);
                float bce = -(ctr_t * __logf(cp) + (1.0f - ctr_t) * __logf(1.0f - cp));

                atomicAdd(&s_conf[b], corr);
                atomicAdd(&s_loc[b],  loss_l);
                atomicAdd(&s_ctr[b],  bce);
                atomicAdd(&s_np[b],   1);
            }
        }
        __syncthreads();

        if (tid < NB) {
            if (s_conf[tid] != 0.0f) atomicAdd(&g_conf[tid], s_conf[tid]);
            if (s_loc[tid]  != 0.0f) atomicAdd(&g_loc[tid],  s_loc[tid]);
            if (s_ctr[tid]  != 0.0f) atomicAdd(&g_ctr[tid],  s_ctr[tid]);
            if (s_np[tid])           atomicAdd(&g_npos[tid], s_np[tid]);
        }
        if (tid < 32 && tid >= NB) { /* keep warp convergent */ }
        if ((tid >> 5) == 0)
            __threadfence();   // release: issuing warp only (1 MEMBAR/block)
    }

    // ============ completion: last-arriving block finalizes ============
    __syncthreads();
    if (tid == 0)
        s_last = (atomicAdd(&g_count, 1u) == (unsigned)(TOTALBLK - 1));
    __syncthreads();

    if (s_last && tid < 32) {
        __threadfence();   // acquire: all prior releases are now visible
        volatile float* vconf = g_conf;
        volatile float* vloc  = g_loc;
        volatile float* vctr  = g_ctr;
        volatile int*   vnp   = g_npos;

        float v = 0.0f;
        if (tid < NB) {
            float lc = vconf[tid], ll = vloc[tid], lctr = vctr[tid];
            int   np = vnp[tid];
            float pf = (float)np;
            v = (np > 0) ? (lctr + (lc + ll) / fmaxf(pf, 1.0f))
                         : (lctr + lc + ll);
        }
        #pragma unroll
        for (int o = 16; o > 0; o >>= 1)
            v += __shfl_down_sync(0xffffffffu, v, o);
        if (tid == 0) out[0] = v * (1.0f / (float)NB);

        // reset state for the next invocation / graph replay
        if (tid < NB) {
            vconf[tid] = 0.0f; vloc[tid] = 0.0f; vctr[tid] = 0.0f; vnp[tid] = 0;
        }
        __threadfence();
        if (tid == 0) g_count = 0u;
    }
}

// ---------------------------------------------------------------------------
extern "C" void kernel_launch(void* const* d_in, const int* in_sizes, int n_in,
                              void* d_out, int out_size)
{
    (void)n_in; (void)out_size;

    // Runtime input-order detection.
    // Per-level order:    in_sizes[1] = 16*4*12800 = 819200   (loc0)
    // Type-grouped order: in_sizes[1] = 16*80*3200 = 4096000  (conf1)
    int iconf[5], iloc[5], ictr[5], iltrb[5], icls[5], ipos[5];
    if (in_sizes[1] == 16 * 4 * 12800) {
        for (int l = 0; l < 5; l++) {
            iconf[l] = 6 * l + 0; iloc[l] = 6 * l + 1; ictr[l] = 6 * l + 2;
            iltrb[l] = 6 * l + 3; icls[l] = 6 * l + 4; ipos[l] = 6 * l + 5;
        }
    } else {
        for (int l = 0; l < 5; l++) {
            iconf[l] = l; iloc[l] = 5 + l; ictr[l] = 10 + l;
            iltrb[l] = 15 + l; icls[l] = 20 + l; ipos[l] = 25 + l;
        }
    }

    fcos_work_kernel<<<TOTALBLK, 256>>>(
        (const float*)d_in[iconf[0]], (const float*)d_in[iconf[1]],
        (const float*)d_in[iconf[2]], (const float*)d_in[iconf[3]],
        (const float*)d_in[iconf[4]],
        (const float*)d_in[iloc[0]],  (const float*)d_in[iloc[1]],
        (const float*)d_in[iloc[2]],  (const float*)d_in[iloc[3]],
        (const float*)d_in[iloc[4]],
        (const float*)d_in[ictr[0]],  (const float*)d_in[ictr[1]],
        (const float*)d_in[ictr[2]],  (const float*)d_in[ictr[3]],
        (const float*)d_in[ictr[4]],
        (const float*)d_in[iltrb[0]], (const float*)d_in[iltrb[1]],
        (const float*)d_in[iltrb[2]], (const float*)d_in[iltrb[3]],
        (const float*)d_in[iltrb[4]],
        (const int*)d_in[icls[0]], (const int*)d_in[icls[1]],
        (const int*)d_in[icls[2]], (const int*)d_in[icls[3]],
        (const int*)d_in[icls[4]],
        (const int*)d_in[ipos[0]], (const int*)d_in[ipos[1]],
        (const int*)d_in[ipos[2]], (const int*)d_in[ipos[3]],
        (const int*)d_in[ipos[4]],
        (float*)d_out);
}